// round 3
// baseline (speedup 1.0000x reference)
#include <cuda_runtime.h>
#include <math.h>

#define B_   4
#define L_   1024
#define DM   256
#define DI   512
#define NS   16
#define DTR  16
#define KC   4
#define NL   8
#define ROWS (B_*L_)

// ---------------- static scratch (no allocs allowed) ----------------
__device__ float g_h[ROWS*DM];        // residual stream
__device__ float g_xn[ROWS*DM];       // rmsnorm output
__device__ float g_hidgate[ROWS*2*DI];// in-proj output: [hid | gate]
__device__ float g_hid[ROWS*DI];      // post conv+silu
__device__ float g_sp[ROWS*48];       // [dt(16) | B(16) | C(16)]
__device__ float g_delta[ROWS*DI];    // softplus(dt@Wdt + b)
__device__ float g_y[ROWS*DI];        // scan output (gated)

// ---------------- embed ----------------
__global__ void embed_kernel(const float* __restrict__ x,
                             const float* __restrict__ pos,
                             const float* __restrict__ We,
                             const float* __restrict__ be) {
    int row = blockIdx.x;          // 0..4095
    int j   = threadIdx.x;         // 0..127
    int l   = row & (L_-1);
    float x0 = x[row*2+0], x1 = x[row*2+1];
    g_h[(size_t)row*DM + j]       = x0*We[j] + x1*We[128+j] + be[j];
    g_h[(size_t)row*DM + 128 + j] = pos[l*128 + j];
}

// ---------------- rmsnorm ----------------
__global__ void __launch_bounds__(256) rmsnorm_kernel(const float* __restrict__ w) {
    int row = blockIdx.x, tid = threadIdx.x;
    float v = g_h[(size_t)row*DM + tid];
    float ss = v*v;
    #pragma unroll
    for (int o = 16; o > 0; o >>= 1) ss += __shfl_xor_sync(0xffffffffu, ss, o);
    __shared__ float red[8];
    if ((tid & 31) == 0) red[tid >> 5] = ss;
    __syncthreads();
    float tot = 0.f;
    #pragma unroll
    for (int i = 0; i < 8; i++) tot += red[i];
    float scale = rsqrtf(tot * (1.f/DM) + 1e-5f);
    g_xn[(size_t)row*DM + tid] = v * scale * w[tid];
}

// ---------------- generic tiled SGEMM body ----------------
// C[M,N] = A[M,K] @ Bw[K,N]  (+Res if RES). 256 threads, 64x64 tile, 4x4 per thread.
template<int M, int N, int K, bool RES>
__device__ __forceinline__ void sgemm_body(const float* __restrict__ A,
                                           const float* __restrict__ Bw,
                                           float* C, const float* Res) {
    constexpr int BM = 64, BN = 64, BK = 16;
    __shared__ float As[BK][BM];
    __shared__ float Bs[BK][BN];
    const int tid = threadIdx.x;
    const int tx = tid & 15;
    const int ty = tid >> 4;
    const int row0 = blockIdx.y * BM;
    const int col0 = blockIdx.x * BN;
    float acc[4][4] = {};
    for (int k0 = 0; k0 < K; k0 += BK) {
        #pragma unroll
        for (int i = tid; i < BM*BK; i += 256) {   // 4 iters
            int m = i >> 4, k = i & 15;
            As[k][m] = A[(size_t)(row0 + m)*K + k0 + k];
        }
        #pragma unroll
        for (int i = tid; i < BK*BN; i += 256) {   // 4 iters
            int k = i >> 6, n = i & 63;
            int gn = col0 + n;
            Bs[k][n] = (gn < N) ? Bw[(size_t)(k0 + k)*N + gn] : 0.f;
        }
        __syncthreads();
        #pragma unroll
        for (int k = 0; k < BK; k++) {
            float4 av = *reinterpret_cast<const float4*>(&As[k][ty*4]);
            float4 bv = *reinterpret_cast<const float4*>(&Bs[k][tx*4]);
            float a[4] = {av.x, av.y, av.z, av.w};
            float b[4] = {bv.x, bv.y, bv.z, bv.w};
            #pragma unroll
            for (int i = 0; i < 4; i++)
                #pragma unroll
                for (int j = 0; j < 4; j++)
                    acc[i][j] = fmaf(a[i], b[j], acc[i][j]);
        }
        __syncthreads();
    }
    #pragma unroll
    for (int i = 0; i < 4; i++) {
        int gm = row0 + ty*4 + i;
        #pragma unroll
        for (int j = 0; j < 4; j++) {
            int gn = col0 + tx*4 + j;
            if (gn < N) {
                float v = acc[i][j];
                if (RES) v += Res[(size_t)gm*N + gn];
                C[(size_t)gm*N + gn] = v;
            }
        }
    }
}

__global__ void __launch_bounds__(256) gemm_in_k(const float* __restrict__ W) {
    sgemm_body<ROWS, 2*DI, DM, false>(g_xn, W, g_hidgate, nullptr);
}
__global__ void __launch_bounds__(256) gemm_x_k(const float* __restrict__ W) {
    sgemm_body<ROWS, 48, DI, false>(g_hid, W, g_sp, nullptr);
}
__global__ void __launch_bounds__(256) gemm_out_k(const float* __restrict__ W) {
    sgemm_body<ROWS, DM, DI, true>(g_y, W, g_h, g_h);
}

// ---------------- causal depthwise conv (K=4) + silu ----------------
__global__ void __launch_bounds__(256) conv_silu_kernel(const float* __restrict__ cw,
                                                        const float* __restrict__ cb) {
    int idx = blockIdx.x*256 + threadIdx.x;      // over ROWS*DI
    int d   = idx & (DI-1);
    int row = idx >> 9;
    int l   = row & (L_-1);
    float c0 = cw[d*KC+0], c1 = cw[d*KC+1], c2 = cw[d*KC+2], c3 = cw[d*KC+3];
    const float* base = g_hidgate + (size_t)row*(2*DI) + d;
    float acc = cb[d];
    if (l >= 3) acc = fmaf(base[-3*2*DI], c0, acc);
    if (l >= 2) acc = fmaf(base[-2*2*DI], c1, acc);
    if (l >= 1) acc = fmaf(base[-1*2*DI], c2, acc);
    acc = fmaf(base[0], c3, acc);
    g_hid[idx] = acc / (1.f + __expf(-acc));     // silu
}

// ---------------- delta = softplus(dt @ Wdt + b_dt) ----------------
__global__ void __launch_bounds__(512) delta_kernel(const float* __restrict__ Wdt,
                                                    const float* __restrict__ bdt) {
    int row = blockIdx.x, d = threadIdx.x;
    __shared__ float dt[DTR];
    if (d < DTR) dt[d] = g_sp[row*48 + d];
    __syncthreads();
    float acc = bdt[d];
    #pragma unroll
    for (int r = 0; r < DTR; r++) acc = fmaf(dt[r], Wdt[r*DI + d], acc);
    g_delta[(size_t)row*DI + d] = (acc > 20.f) ? acc : log1pf(__expf(acc));
}

// ---------------- selective scan + skip + gate ----------------
// block = (b, 16-channel d-tile); threads: n = tid&15, dl = tid>>4
#define CH 16
__global__ void __launch_bounds__(256) scan_kernel(const float* __restrict__ Alog,
                                                   const float* __restrict__ Dsk) {
    const int b    = blockIdx.x >> 5;     // DI/16 = 32 tiles
    const int dblk = blockIdx.x & 31;
    const int tid  = threadIdx.x;
    const int n    = tid & 15;
    const int dl   = tid >> 4;
    const int d    = dblk*16 + dl;
    const float A  = -__expf(Alog[d*NS + n]);
    const float Dskip = Dsk[d];
    float h = 0.f;
    __shared__ float s_delta[CH][16], s_hid[CH][16], s_B[CH][16],
                     s_C[CH][16], s_gate[CH][16], s_y[CH][16];
    for (int t0 = 0; t0 < L_; t0 += CH) {
        __syncthreads();
        {   // stage CH timesteps; 256 threads, one element each per array
            int tt = tid >> 4, c = tid & 15;
            int row = b*L_ + t0 + tt;
            s_delta[tt][c] = g_delta[(size_t)row*DI + dblk*16 + c];
            s_hid[tt][c]   = g_hid  [(size_t)row*DI + dblk*16 + c];
            s_B[tt][c]     = g_sp[row*48 + DTR + c];
            s_C[tt][c]     = g_sp[row*48 + DTR + NS + c];
            s_gate[tt][c]  = g_hidgate[(size_t)row*(2*DI) + DI + dblk*16 + c];
        }
        __syncthreads();
        #pragma unroll
        for (int tt = 0; tt < CH; tt++) {
            float de  = s_delta[tt][dl];
            float dA  = __expf(de * A);
            float dBu = de * s_B[tt][n] * s_hid[tt][dl];
            h = fmaf(dA, h, dBu);
            float contrib = h * s_C[tt][n];
            contrib += __shfl_xor_sync(0xffffffffu, contrib, 1);
            contrib += __shfl_xor_sync(0xffffffffu, contrib, 2);
            contrib += __shfl_xor_sync(0xffffffffu, contrib, 4);
            contrib += __shfl_xor_sync(0xffffffffu, contrib, 8);
            if (n == 0) {
                float yv = contrib + s_hid[tt][dl]*Dskip;
                float g  = s_gate[tt][dl];
                s_y[tt][dl] = yv * g / (1.f + __expf(-g));
            }
        }
        __syncthreads();
        {   // coalesced write of gated scan output
            int tt = tid >> 4, c = tid & 15;
            int row = b*L_ + t0 + tt;
            g_y[(size_t)row*DI + dblk*16 + c] = s_y[tt][c];
        }
    }
}

// ---------------- output head ----------------
__global__ void __launch_bounds__(256) head_kernel(const float* __restrict__ Wa,
                                                   const float* __restrict__ ba,
                                                   const float* __restrict__ Wp,
                                                   const float* __restrict__ bp,
                                                   float* __restrict__ out) {
    int row = blockIdx.x, tid = threadIdx.x;
    float v  = g_h[(size_t)row*DM + tid];
    float pa = v * Wa[tid];
    float pp = v * Wp[tid];
    #pragma unroll
    for (int o = 16; o > 0; o >>= 1) {
        pa += __shfl_xor_sync(0xffffffffu, pa, o);
        pp += __shfl_xor_sync(0xffffffffu, pp, o);
    }
    __shared__ float ra[8], rp[8];
    if ((tid & 31) == 0) { ra[tid>>5] = pa; rp[tid>>5] = pp; }
    __syncthreads();
    if (tid == 0) {
        float sa = 0.f, sp2 = 0.f;
        #pragma unroll
        for (int i = 0; i < 8; i++) { sa += ra[i]; sp2 += rp[i]; }
        out[row*2+0] = sa + ba[0];
        out[row*2+1] = tanhf(sp2 + bp[0]);
    }
}

// ---------------- launch ----------------
extern "C" void kernel_launch(void* const* d_in, const int* in_sizes, int n_in,
                              void* d_out, int out_size) {
    const float* x       = (const float*)d_in[0];
    const float* pos     = (const float*)d_in[1];
    const float* W_embed = (const float*)d_in[2];
    const float* b_embed = (const float*)d_in[3];
    const float* ln_w    = (const float*)d_in[4];
    const float* W_in    = (const float*)d_in[5];
    const float* conv_w  = (const float*)d_in[6];
    const float* conv_b  = (const float*)d_in[7];
    const float* W_x     = (const float*)d_in[8];
    const float* W_dt    = (const float*)d_in[9];
    const float* b_dt    = (const float*)d_in[10];
    const float* A_log   = (const float*)d_in[11];
    const float* D_skip  = (const float*)d_in[12];
    const float* W_out   = (const float*)d_in[13];
    const float* W_amp   = (const float*)d_in[14];
    const float* b_amp   = (const float*)d_in[15];
    const float* W_phase = (const float*)d_in[16];
    const float* b_phase = (const float*)d_in[17];

    embed_kernel<<<ROWS, 128>>>(x, pos, W_embed, b_embed);

    for (int i = 0; i < NL; i++) {
        rmsnorm_kernel<<<ROWS, 256>>>(ln_w + (size_t)i*DM);
        gemm_in_k<<<dim3((2*DI)/64, ROWS/64), 256>>>(W_in + (size_t)i*DM*2*DI);
        conv_silu_kernel<<<(ROWS*DI)/256, 256>>>(conv_w + (size_t)i*DI*KC,
                                                 conv_b + (size_t)i*DI);
        gemm_x_k<<<dim3(1, ROWS/64), 256>>>(W_x + (size_t)i*DI*48);
        delta_kernel<<<ROWS, DI>>>(W_dt + (size_t)i*DTR*DI, b_dt + (size_t)i*DI);
        scan_kernel<<<B_*(DI/16), 256>>>(A_log + (size_t)i*DI*NS,
                                         D_skip + (size_t)i*DI);
        gemm_out_k<<<dim3(DM/64, ROWS/64), 256>>>(W_out + (size_t)i*DI*DM);
    }

    head_kernel<<<ROWS, 256>>>(W_amp, b_amp, W_phase, b_phase, (float*)d_out);
}

// round 4
// speedup vs baseline: 1.3209x; 1.3209x over previous
#include <cuda_runtime.h>
#include <math.h>
#include <stdint.h>

#define B_   4
#define L_   1024
#define DM   256
#define DI   512
#define NS   16
#define DTR  16
#define KC   4
#define NL   8
#define ROWS (B_*L_)

// ---------------- static scratch (no allocs allowed) ----------------
__device__ float g_h[ROWS*DM];        // residual stream
__device__ float g_xn[ROWS*DM];       // rmsnorm output
__device__ float g_hidgate[ROWS*2*DI];// in-proj output: [hid | gate]
__device__ float g_hid[ROWS*DI];      // post conv+silu
__device__ float g_sp[ROWS*48];       // [dt(16) | B(16) | C(16)]
__device__ float g_delta[ROWS*DI];    // softplus(dt@Wdt + b)
__device__ float g_y[ROWS*DI];        // scan output (gated)

// ---------------- embed ----------------
__global__ void embed_kernel(const float* __restrict__ x,
                             const float* __restrict__ pos,
                             const float* __restrict__ We,
                             const float* __restrict__ be) {
    int row = blockIdx.x;          // 0..4095
    int j   = threadIdx.x;         // 0..127
    int l   = row & (L_-1);
    float x0 = x[row*2+0], x1 = x[row*2+1];
    g_h[(size_t)row*DM + j]       = x0*We[j] + x1*We[128+j] + be[j];
    g_h[(size_t)row*DM + 128 + j] = pos[l*128 + j];
}

// ---------------- rmsnorm ----------------
__global__ void __launch_bounds__(256) rmsnorm_kernel(const float* __restrict__ w) {
    int row = blockIdx.x, tid = threadIdx.x;
    float v = g_h[(size_t)row*DM + tid];
    float ss = v*v;
    #pragma unroll
    for (int o = 16; o > 0; o >>= 1) ss += __shfl_xor_sync(0xffffffffu, ss, o);
    __shared__ float red[8];
    if ((tid & 31) == 0) red[tid >> 5] = ss;
    __syncthreads();
    float tot = 0.f;
    #pragma unroll
    for (int i = 0; i < 8; i++) tot += red[i];
    float scale = rsqrtf(tot * (1.f/DM) + 1e-5f);
    g_xn[(size_t)row*DM + tid] = v * scale * w[tid];
}

// ---------------- tf32 tensor-core GEMM with error-free split ----------------
__device__ __forceinline__ uint32_t f2tf32(float x) {
    uint32_t r;
    asm("cvt.rna.tf32.f32 %0, %1;" : "=r"(r) : "f"(x));
    return r;
}
__device__ __forceinline__ void split_tf32(float x, uint32_t& hi, uint32_t& lo) {
    hi = f2tf32(x);
    float hif = __uint_as_float(hi);
    lo = f2tf32(x - hif);
}
__device__ __forceinline__ void mma_tf32(float& c0, float& c1, float& c2, float& c3,
                                         uint32_t a0, uint32_t a1, uint32_t a2, uint32_t a3,
                                         uint32_t b0, uint32_t b1) {
    asm volatile(
        "mma.sync.aligned.m16n8k8.row.col.f32.tf32.tf32.f32 "
        "{%0,%1,%2,%3}, {%4,%5,%6,%7}, {%8,%9}, {%0,%1,%2,%3};"
        : "+f"(c0), "+f"(c1), "+f"(c2), "+f"(c3)
        : "r"(a0), "r"(a1), "r"(a2), "r"(a3), "r"(b0), "r"(b1));
}

// C[M,N] = A[M,K] @ W[K,N] (+Res if RES). Block 64x64x32, 256 threads (8 warps 4x2).
// Each warp: 16 rows x 32 cols = 4 m16n8k8 n-tiles. 3 mma per tile (split precision).
template<int N_, int K_, bool RES>
__device__ __forceinline__ void mma_gemm_body(const float* __restrict__ A,
                                              const float* __restrict__ W,
                                              float* C, const float* Res) {
    __shared__ float As[64][36];   // pad 4: stride 36
    __shared__ float Bs[32][72];   // pad 8: stride 72 -> conflict-free frag loads
    const int tid  = threadIdx.x;
    const int lane = tid & 31;
    const int warp = tid >> 5;
    const int wr   = warp & 3;     // warp row: 16 rows each
    const int wc   = warp >> 2;    // warp col: 32 cols each
    const int row0 = blockIdx.y * 64;
    const int col0 = blockIdx.x * 64;

    float acc[4][4] = {};

    for (int k0 = 0; k0 < K_; k0 += 32) {
        // stage A: 64x32 floats as float4 (512 float4, 2/thread)
        #pragma unroll
        for (int it = 0; it < 2; it++) {
            int idx = tid + it*256;
            int r = idx >> 3, k4 = idx & 7;
            float4 v = *reinterpret_cast<const float4*>(
                A + (size_t)(row0 + r)*K_ + k0 + k4*4);
            *reinterpret_cast<float4*>(&As[r][k4*4]) = v;
        }
        // stage B: 32x64 floats as float4 (512 float4, 2/thread), guard N
        #pragma unroll
        for (int it = 0; it < 2; it++) {
            int idx = tid + it*256;
            int k = idx >> 4, n4 = idx & 15;
            int gn = col0 + n4*4;
            float4 v;
            if ((N_ & 63) == 0 || gn + 3 < N_)
                v = *reinterpret_cast<const float4*>(W + (size_t)(k0 + k)*N_ + gn);
            else
                v = make_float4(0.f, 0.f, 0.f, 0.f);
            *reinterpret_cast<float4*>(&Bs[k][n4*4]) = v;
        }
        __syncthreads();

        #pragma unroll
        for (int ks = 0; ks < 4; ks++) {
            const int rb = wr*16 + (lane >> 2);
            const int kk = ks*8 + (lane & 3);
            uint32_t ah[4], al[4];
            split_tf32(As[rb    ][kk    ], ah[0], al[0]);
            split_tf32(As[rb + 8][kk    ], ah[1], al[1]);
            split_tf32(As[rb    ][kk + 4], ah[2], al[2]);
            split_tf32(As[rb + 8][kk + 4], ah[3], al[3]);
            #pragma unroll
            for (int nt = 0; nt < 4; nt++) {
                const int cb = wc*32 + nt*8 + (lane >> 2);
                uint32_t bh0, bl0, bh1, bl1;
                split_tf32(Bs[ks*8 + (lane & 3)    ][cb], bh0, bl0);
                split_tf32(Bs[ks*8 + (lane & 3) + 4][cb], bh1, bl1);
                mma_tf32(acc[nt][0], acc[nt][1], acc[nt][2], acc[nt][3],
                         ah[0], ah[1], ah[2], ah[3], bh0, bh1);
                mma_tf32(acc[nt][0], acc[nt][1], acc[nt][2], acc[nt][3],
                         ah[0], ah[1], ah[2], ah[3], bl0, bl1);
                mma_tf32(acc[nt][0], acc[nt][1], acc[nt][2], acc[nt][3],
                         al[0], al[1], al[2], al[3], bh0, bh1);
            }
        }
        __syncthreads();
    }

    // epilogue: c0: (r, 2q) c1: (r, 2q+1) c2/c3: (+8 rows)
    const int r0 = row0 + wr*16 + (lane >> 2);
    #pragma unroll
    for (int nt = 0; nt < 4; nt++) {
        const int cbase = col0 + wc*32 + nt*8 + 2*(lane & 3);
        #pragma unroll
        for (int h = 0; h < 2; h++) {          // row group (+0 / +8)
            int gm = r0 + h*8;
            #pragma unroll
            for (int q = 0; q < 2; q++) {      // col (+0 / +1)
                int gn = cbase + q;
                if ((N_ & 63) == 0 || gn < N_) {
                    float v = acc[nt][h*2 + q];
                    if (RES) v += Res[(size_t)gm*N_ + gn];
                    C[(size_t)gm*N_ + gn] = v;
                }
            }
        }
    }
}

__global__ void __launch_bounds__(256) gemm_in_k(const float* __restrict__ W) {
    mma_gemm_body<2*DI, DM, false>(g_xn, W, g_hidgate, nullptr);
}
__global__ void __launch_bounds__(256) gemm_x_k(const float* __restrict__ W) {
    mma_gemm_body<48, DI, false>(g_hid, W, g_sp, nullptr);
}
__global__ void __launch_bounds__(256) gemm_out_k(const float* __restrict__ W) {
    mma_gemm_body<DM, DI, true>(g_y, W, g_h, g_h);
}

// ---------------- causal depthwise conv (K=4) + silu ----------------
__global__ void __launch_bounds__(256) conv_silu_kernel(const float* __restrict__ cw,
                                                        const float* __restrict__ cb) {
    int idx = blockIdx.x*256 + threadIdx.x;      // over ROWS*DI
    int d   = idx & (DI-1);
    int row = idx >> 9;
    int l   = row & (L_-1);
    float c0 = cw[d*KC+0], c1 = cw[d*KC+1], c2 = cw[d*KC+2], c3 = cw[d*KC+3];
    const float* base = g_hidgate + (size_t)row*(2*DI) + d;
    float acc = cb[d];
    if (l >= 3) acc = fmaf(base[-3*2*DI], c0, acc);
    if (l >= 2) acc = fmaf(base[-2*2*DI], c1, acc);
    if (l >= 1) acc = fmaf(base[-1*2*DI], c2, acc);
    acc = fmaf(base[0], c3, acc);
    g_hid[idx] = acc / (1.f + __expf(-acc));     // silu
}

// ---------------- delta = softplus(dt @ Wdt + b_dt) ----------------
__global__ void __launch_bounds__(512) delta_kernel(const float* __restrict__ Wdt,
                                                    const float* __restrict__ bdt) {
    int row = blockIdx.x, d = threadIdx.x;
    __shared__ float dt[DTR];
    if (d < DTR) dt[d] = g_sp[row*48 + d];
    __syncthreads();
    float acc = bdt[d];
    #pragma unroll
    for (int r = 0; r < DTR; r++) acc = fmaf(dt[r], Wdt[r*DI + d], acc);
    g_delta[(size_t)row*DI + d] = (acc > 20.f) ? acc : log1pf(__expf(acc));
}

// ---------------- selective scan + skip + gate ----------------
#define CH 16
__global__ void __launch_bounds__(256) scan_kernel(const float* __restrict__ Alog,
                                                   const float* __restrict__ Dsk) {
    const int b    = blockIdx.x >> 5;     // DI/16 = 32 tiles
    const int dblk = blockIdx.x & 31;
    const int tid  = threadIdx.x;
    const int n    = tid & 15;
    const int dl   = tid >> 4;
    const int d    = dblk*16 + dl;
    const float A  = -__expf(Alog[d*NS + n]);
    const float Dskip = Dsk[d];
    float h = 0.f;
    __shared__ float s_delta[CH][16], s_hid[CH][16], s_B[CH][16],
                     s_C[CH][16], s_gate[CH][16], s_y[CH][16];
    for (int t0 = 0; t0 < L_; t0 += CH) {
        __syncthreads();
        {
            int tt = tid >> 4, c = tid & 15;
            int row = b*L_ + t0 + tt;
            s_delta[tt][c] = g_delta[(size_t)row*DI + dblk*16 + c];
            s_hid[tt][c]   = g_hid  [(size_t)row*DI + dblk*16 + c];
            s_B[tt][c]     = g_sp[row*48 + DTR + c];
            s_C[tt][c]     = g_sp[row*48 + DTR + NS + c];
            s_gate[tt][c]  = g_hidgate[(size_t)row*(2*DI) + DI + dblk*16 + c];
        }
        __syncthreads();
        #pragma unroll
        for (int tt = 0; tt < CH; tt++) {
            float de  = s_delta[tt][dl];
            float dA  = __expf(de * A);
            float dBu = de * s_B[tt][n] * s_hid[tt][dl];
            h = fmaf(dA, h, dBu);
            float contrib = h * s_C[tt][n];
            contrib += __shfl_xor_sync(0xffffffffu, contrib, 1);
            contrib += __shfl_xor_sync(0xffffffffu, contrib, 2);
            contrib += __shfl_xor_sync(0xffffffffu, contrib, 4);
            contrib += __shfl_xor_sync(0xffffffffu, contrib, 8);
            if (n == 0) {
                float yv = contrib + s_hid[tt][dl]*Dskip;
                float g  = s_gate[tt][dl];
                s_y[tt][dl] = yv * g / (1.f + __expf(-g));
            }
        }
        __syncthreads();
        {
            int tt = tid >> 4, c = tid & 15;
            int row = b*L_ + t0 + tt;
            g_y[(size_t)row*DI + dblk*16 + c] = s_y[tt][c];
        }
    }
}

// ---------------- output head ----------------
__global__ void __launch_bounds__(256) head_kernel(const float* __restrict__ Wa,
                                                   const float* __restrict__ ba,
                                                   const float* __restrict__ Wp,
                                                   const float* __restrict__ bp,
                                                   float* __restrict__ out) {
    int row = blockIdx.x, tid = threadIdx.x;
    float v  = g_h[(size_t)row*DM + tid];
    float pa = v * Wa[tid];
    float pp = v * Wp[tid];
    #pragma unroll
    for (int o = 16; o > 0; o >>= 1) {
        pa += __shfl_xor_sync(0xffffffffu, pa, o);
        pp += __shfl_xor_sync(0xffffffffu, pp, o);
    }
    __shared__ float ra[8], rp[8];
    if ((tid & 31) == 0) { ra[tid>>5] = pa; rp[tid>>5] = pp; }
    __syncthreads();
    if (tid == 0) {
        float sa = 0.f, sp2 = 0.f;
        #pragma unroll
        for (int i = 0; i < 8; i++) { sa += ra[i]; sp2 += rp[i]; }
        out[row*2+0] = sa + ba[0];
        out[row*2+1] = tanhf(sp2 + bp[0]);
    }
}

// ---------------- launch ----------------
extern "C" void kernel_launch(void* const* d_in, const int* in_sizes, int n_in,
                              void* d_out, int out_size) {
    const float* x       = (const float*)d_in[0];
    const float* pos     = (const float*)d_in[1];
    const float* W_embed = (const float*)d_in[2];
    const float* b_embed = (const float*)d_in[3];
    const float* ln_w    = (const float*)d_in[4];
    const float* W_in    = (const float*)d_in[5];
    const float* conv_w  = (const float*)d_in[6];
    const float* conv_b  = (const float*)d_in[7];
    const float* W_x     = (const float*)d_in[8];
    const float* W_dt    = (const float*)d_in[9];
    const float* b_dt    = (const float*)d_in[10];
    const float* A_log   = (const float*)d_in[11];
    const float* D_skip  = (const float*)d_in[12];
    const float* W_out   = (const float*)d_in[13];
    const float* W_amp   = (const float*)d_in[14];
    const float* b_amp   = (const float*)d_in[15];
    const float* W_phase = (const float*)d_in[16];
    const float* b_phase = (const float*)d_in[17];

    embed_kernel<<<ROWS, 128>>>(x, pos, W_embed, b_embed);

    for (int i = 0; i < NL; i++) {
        rmsnorm_kernel<<<ROWS, 256>>>(ln_w + (size_t)i*DM);
        gemm_in_k<<<dim3((2*DI)/64, ROWS/64), 256>>>(W_in + (size_t)i*DM*2*DI);
        conv_silu_kernel<<<(ROWS*DI)/256, 256>>>(conv_w + (size_t)i*DI*KC,
                                                 conv_b + (size_t)i*DI);
        gemm_x_k<<<dim3(1, ROWS/64), 256>>>(W_x + (size_t)i*DI*48);
        delta_kernel<<<ROWS, DI>>>(W_dt + (size_t)i*DTR*DI, b_dt + (size_t)i*DI);
        scan_kernel<<<B_*(DI/16), 256>>>(A_log + (size_t)i*DI*NS,
                                         D_skip + (size_t)i*DI);
        gemm_out_k<<<dim3(DM/64, ROWS/64), 256>>>(W_out + (size_t)i*DI*DM);
    }

    head_kernel<<<ROWS, 256>>>(W_amp, b_amp, W_phase, b_phase, (float*)d_out);
}